// round 9
// baseline (speedup 1.0000x reference)
#include <cuda_runtime.h>
#include <cuda_bf16.h>
#include <cstdint>

// -----------------------------------------------------------------------------
// OConnorWeatherall belief update, N=500000, K=64, TRIALS=10.
//
// Reference hypothesis: GPU jax (XLA:GPU) in this container. Replicated
// arithmetic, per NVPTX DAGCombiner contraction (AllowFPOpFusion::Fast, NO
// aggressive multi-use fusion -> hasOneUse rule):
//   pl   = rn(prior*lik)                      // two uses -> NOT fused
//   marg = fma(1-prior, alt, pl)              // N1-side fusion (single-use mul)
//   cert = max(fma(-(delta*mst), 1-marg, 1), 0)
//   post = fma(bel, cert, rn(mis*(1-cert)))
//   divisions: div.rn.f32 (__fdiv_rn); pow: libdevice __nv_powf (XLA:GPU).
//
// Memory plan:
//   pack_kernel: records[i] = { belief bits, active<<8 | s }  (8B -> 1 L2 sector)
//   fold_kernel: 1 thread/node, 11-entry likelihood table in a private smem
//   column (conflict-free, no syncs), int4 nbr stream (__ldcs), 2-deep prefetch.
// -----------------------------------------------------------------------------

extern "C" __device__ float __nv_powf(float, float);   // libdevice (XLA:GPU pow)

#define MAXN 500000
#define BLK  256

__device__ __align__(8) static uint2 g_records[MAXN];

__global__ void pack_kernel(const float* __restrict__ belief,
                            const float* __restrict__ payoff,
                            int n) {
    int i = blockIdx.x * blockDim.x + threadIdx.x;
    if (i >= n) return;
    float s = payoff[2 * i];
    float t = payoff[2 * i + 1];
    unsigned meta = 0u;
    if (t > 0.0f) {
        meta = 0x100u | (unsigned)__float2int_rn(s);
    }
    g_records[i] = make_uint2(__float_as_uint(belief[i]), meta);
}

// One fold step: NVPTX hasOneUse-contracted tree.
__device__ __forceinline__ float fold_step(float prior, uint2 rec,
                                           const float* __restrict__ T,
                                           float mst) {
    unsigned meta = rec.y;
    if (meta & 0x100u) {
        float b   = __uint_as_float(rec.x);
        int   s   = (int)(meta & 0xFFu);
        float lik = T[s * BLK];
        float alt = T[(10 - s) * BLK];
        float delta = fabsf(__fsub_rn(prior, b));
        float pl    = __fmul_rn(prior, lik);          // 2 uses -> stays a mul
        // fadd(mul1=pl, mul2=(1-prior)*alt): mul1 multi-use -> fuse mul2 side:
        float marg  = __fmaf_rn(__fsub_rn(1.0f, prior), alt, pl);
        float omm   = __fsub_rn(1.0f, marg);
        float bel   = __fdiv_rn(pl, marg);
        float mis   = __fdiv_rn(__fmul_rn(prior, __fsub_rn(1.0f, lik)), omm);
        // fsub(1, fmul(u, omm)) -> fma(-u, omm, 1)
        float u     = __fmul_rn(delta, mst);
        float cert  = fmaxf(__fmaf_rn(-u, omm, 1.0f), 0.0f);
        // fadd(mul(bel,cert), mul(mis,1-cert)) -> fuse N0:
        prior = __fmaf_rn(bel, cert,
                          __fmul_rn(mis, __fsub_rn(1.0f, cert)));
    }
    return prior;
}

__global__ __launch_bounds__(BLK)
void fold_kernel(const float* __restrict__ belief,
                 const float* __restrict__ prob,
                 const float* __restrict__ mistrust,
                 const int*   __restrict__ nbr,
                 float*       __restrict__ out,
                 int n) {
    __shared__ float Tsh[11 * BLK];
    int tid = threadIdx.x;
    int i = blockIdx.x * BLK + tid;
    bool valid = (i < n);

    float p = valid ? prob[i] : 0.7f;
    float q = __fsub_rn(1.0f, p);

    // T[s] = rn( __nv_powf(p,s) * __nv_powf(q,10-s) )  — XLA:GPU's lik tree.
    {
        float* Tt = Tsh + tid;
#pragma unroll
        for (int s = 0; s <= 10; ++s) {
            float ps = __nv_powf(p, (float)s);
            float qf = __nv_powf(q, (float)(10 - s));
            Tt[s * BLK] = __fmul_rn(ps, qf);
        }
    }
    if (!valid) return;   // private smem columns: no __syncthreads needed

    const float* Tt = Tsh + tid;
    float prior = belief[i];
    float mst   = mistrust[i];

    const int4* nrow = (const int4*)(nbr + (long long)i * 64);

    int4 cur = __ldcs(nrow + 0);
    int4 nxt = __ldcs(nrow + 1);
    uint2 r0 = __ldg(&g_records[cur.x]);
    uint2 r1 = __ldg(&g_records[cur.y]);
    uint2 r2 = __ldg(&g_records[cur.z]);
    uint2 r3 = __ldg(&g_records[cur.w]);

#pragma unroll
    for (int g = 0; g < 16; ++g) {
        uint2 s0, s1, s2, s3;
        int4  nn = nxt;
        if (g < 15) {
            s0 = __ldg(&g_records[nxt.x]);
            s1 = __ldg(&g_records[nxt.y]);
            s2 = __ldg(&g_records[nxt.z]);
            s3 = __ldg(&g_records[nxt.w]);
            if (g < 14) nn = __ldcs(nrow + g + 2);
        }
        prior = fold_step(prior, r0, Tt, mst);
        prior = fold_step(prior, r1, Tt, mst);
        prior = fold_step(prior, r2, Tt, mst);
        prior = fold_step(prior, r3, Tt, mst);
        if (g < 15) { r0 = s0; r1 = s1; r2 = s2; r3 = s3; nxt = nn; }
    }

    out[i] = prior;
}

// Generic fallback for unexpected shapes: same tree, direct gathers.
__global__ void fold_generic_kernel(const float* __restrict__ belief,
                                    const float* __restrict__ prob,
                                    const float* __restrict__ mistrust,
                                    const float* __restrict__ payoff,
                                    const int*   __restrict__ nbr,
                                    float*       __restrict__ out,
                                    int n, int K) {
    int i = blockIdx.x * blockDim.x + threadIdx.x;
    if (i >= n) return;
    float p = prob[i];
    float q = __fsub_rn(1.0f, p);
    float mst = mistrust[i];
    float prior = belief[i];
    for (int k = 0; k < K; ++k) {
        int j = nbr[(long long)i * K + k];
        float t = payoff[2 * j + 1];
        if (t > 0.0f) {
            float s = payoff[2 * j];
            float f = __fsub_rn(t, s);
            float b = belief[j];
            float lik = __fmul_rn(__nv_powf(p, s), __nv_powf(q, f));
            float alt = __fmul_rn(__nv_powf(q, s), __nv_powf(p, f));
            float delta = fabsf(__fsub_rn(prior, b));
            float pl    = __fmul_rn(prior, lik);
            float marg  = __fmaf_rn(__fsub_rn(1.0f, prior), alt, pl);
            float omm   = __fsub_rn(1.0f, marg);
            float bel   = __fdiv_rn(pl, marg);
            float mis   = __fdiv_rn(__fmul_rn(prior, __fsub_rn(1.0f, lik)), omm);
            float u     = __fmul_rn(delta, mst);
            float cert  = fmaxf(__fmaf_rn(-u, omm, 1.0f), 0.0f);
            prior = __fmaf_rn(bel, cert,
                              __fmul_rn(mis, __fsub_rn(1.0f, cert)));
        }
    }
    out[i] = prior;
}

extern "C" void kernel_launch(void* const* d_in, const int* in_sizes, int n_in,
                              void* d_out, int out_size) {
    const float* belief   = (const float*)d_in[0];
    const float* prob     = (const float*)d_in[1];
    const float* mistrust = (const float*)d_in[2];
    const float* payoff   = (const float*)d_in[3];
    const int*   nbr      = (const int*)d_in[4];
    float*       out      = (float*)d_out;

    int n = in_sizes[0];
    int K = (n > 0) ? (in_sizes[4] / n) : 0;

    int grid = (n + BLK - 1) / BLK;

    if (K == 64 && n <= MAXN) {
        pack_kernel<<<grid, BLK>>>(belief, payoff, n);
        fold_kernel<<<grid, BLK>>>(belief, prob, mistrust, nbr, out, n);
    } else {
        fold_generic_kernel<<<grid, BLK>>>(belief, prob, mistrust, payoff, nbr,
                                           out, n, K);
    }
}

// round 10
// speedup vs baseline: 1.1286x; 1.1286x over previous
#include <cuda_runtime.h>
#include <cuda_bf16.h>
#include <cstdint>

// -----------------------------------------------------------------------------
// OConnorWeatherall belief update, N=500000, K=64, TRIALS=10.
//
// PASSING arithmetic (R9, bit-exact vs GPU-jax/XLA:GPU — DO NOT CHANGE):
//   pl   = rn(prior*lik)                      // two uses -> NOT fused (NVPTX)
//   marg = fma(1-prior, alt, pl)              // N1-side fusion
//   cert = max(fma(-(delta*mst), 1-marg, 1), 0)
//   post = fma(bel, cert, rn(mis*(1-cert)))
//   div.rn (__fdiv_rn); pow = libdevice __nv_powf.
//
// R10 perf changes (L1TEX was 76.6% and binding):
//   - (lik, alt) packed as float2 in smem -> 1 LDS.64 per step (was 2 LDS.32)
//   - depth-8 record pipeline: two 4-record groups in flight, nbr row 3 ahead
//   - pack kernel reads payoff as float2
// -----------------------------------------------------------------------------

extern "C" __device__ float __nv_powf(float, float);   // libdevice (XLA:GPU pow)

#define MAXN 500000
#define BLK  256

__device__ __align__(8) static uint2 g_records[MAXN];

__global__ void pack_kernel(const float* __restrict__ belief,
                            const float2* __restrict__ payoff,
                            int n) {
    int i = blockIdx.x * blockDim.x + threadIdx.x;
    if (i >= n) return;
    float2 st = payoff[i];
    unsigned meta = 0u;
    if (st.y > 0.0f) {
        meta = 0x100u | (unsigned)__float2int_rn(st.x);
    }
    g_records[i] = make_uint2(__float_as_uint(belief[i]), meta);
}

// One fold step: NVPTX hasOneUse-contracted tree (bit-exact, frozen).
// T = thread's private float2 smem column, stride BLK: T[s] = (lik_s, alt_s).
__device__ __forceinline__ float fold_step(float prior, uint2 rec,
                                           const float2* __restrict__ T,
                                           float mst) {
    unsigned meta = rec.y;
    if (meta & 0x100u) {
        float b   = __uint_as_float(rec.x);
        int   s   = (int)(meta & 0xFFu);
        float2 la = T[s * BLK];
        float lik = la.x;
        float alt = la.y;
        float delta = fabsf(__fsub_rn(prior, b));
        float pl    = __fmul_rn(prior, lik);          // 2 uses -> stays a mul
        float marg  = __fmaf_rn(__fsub_rn(1.0f, prior), alt, pl);
        float omm   = __fsub_rn(1.0f, marg);
        float bel   = __fdiv_rn(pl, marg);
        float mis   = __fdiv_rn(__fmul_rn(prior, __fsub_rn(1.0f, lik)), omm);
        float u     = __fmul_rn(delta, mst);
        float cert  = fmaxf(__fmaf_rn(-u, omm, 1.0f), 0.0f);
        prior = __fmaf_rn(bel, cert,
                          __fmul_rn(mis, __fsub_rn(1.0f, cert)));
    }
    return prior;
}

__global__ __launch_bounds__(BLK)
void fold_kernel(const float* __restrict__ belief,
                 const float* __restrict__ prob,
                 const float* __restrict__ mistrust,
                 const int*   __restrict__ nbr,
                 float*       __restrict__ out,
                 int n) {
    __shared__ float2 Tsh[11 * BLK];
    int tid = threadIdx.x;
    int i = blockIdx.x * BLK + tid;
    bool valid = (i < n);

    float p = valid ? prob[i] : 0.7f;
    float q = __fsub_rn(1.0f, p);

    // lik[s] = rn( __nv_powf(p,s) * __nv_powf(q,10-s) ); alt[s] = lik[10-s].
    {
        float L[11];
#pragma unroll
        for (int s = 0; s <= 10; ++s) {
            float ps = __nv_powf(p, (float)s);
            float qf = __nv_powf(q, (float)(10 - s));
            L[s] = __fmul_rn(ps, qf);
        }
        float2* Tt = Tsh + tid;
#pragma unroll
        for (int s = 0; s <= 10; ++s) {
            Tt[s * BLK] = make_float2(L[s], L[10 - s]);
        }
    }
    if (!valid) return;   // private smem columns: no __syncthreads needed

    const float2* Tt = Tsh + tid;
    float prior = belief[i];
    float mst   = mistrust[i];

    const int4* nrow = (const int4*)(nbr + (long long)i * 64);

    // Depth-8 pipeline: groups g (A, resident), g+1 (B, arriving/resident),
    // g+2 (C, issued this iteration). n2 holds the nbr row for group g+2.
    int4 n2 = __ldcs(nrow + 2);
    int4 r01 = __ldcs(nrow + 0);
    int4 r11 = __ldcs(nrow + 1);
    uint2 A0 = __ldg(&g_records[r01.x]);
    uint2 A1 = __ldg(&g_records[r01.y]);
    uint2 A2 = __ldg(&g_records[r01.z]);
    uint2 A3 = __ldg(&g_records[r01.w]);
    uint2 B0 = __ldg(&g_records[r11.x]);
    uint2 B1 = __ldg(&g_records[r11.y]);
    uint2 B2 = __ldg(&g_records[r11.z]);
    uint2 B3 = __ldg(&g_records[r11.w]);

#pragma unroll
    for (int g = 0; g < 16; ++g) {
        uint2 C0, C1, C2, C3;
        int4  nn = n2;
        if (g <= 13) {                       // gather group g+2
            C0 = __ldg(&g_records[n2.x]);
            C1 = __ldg(&g_records[n2.y]);
            C2 = __ldg(&g_records[n2.z]);
            C3 = __ldg(&g_records[n2.w]);
        }
        if (g <= 12) nn = __ldcs(nrow + g + 3);   // nbr row for group g+3

        prior = fold_step(prior, A0, Tt, mst);
        prior = fold_step(prior, A1, Tt, mst);
        prior = fold_step(prior, A2, Tt, mst);
        prior = fold_step(prior, A3, Tt, mst);

        if (g <= 13) {
            A0 = B0; A1 = B1; A2 = B2; A3 = B3;
            B0 = C0; B1 = C1; B2 = C2; B3 = C3;
        } else {
            A0 = B0; A1 = B1; A2 = B2; A3 = B3;
        }
        n2 = nn;
    }

    out[i] = prior;
}

// Generic fallback for unexpected shapes: same (frozen) tree, direct gathers.
__global__ void fold_generic_kernel(const float* __restrict__ belief,
                                    const float* __restrict__ prob,
                                    const float* __restrict__ mistrust,
                                    const float* __restrict__ payoff,
                                    const int*   __restrict__ nbr,
                                    float*       __restrict__ out,
                                    int n, int K) {
    int i = blockIdx.x * blockDim.x + threadIdx.x;
    if (i >= n) return;
    float p = prob[i];
    float q = __fsub_rn(1.0f, p);
    float mst = mistrust[i];
    float prior = belief[i];
    for (int k = 0; k < K; ++k) {
        int j = nbr[(long long)i * K + k];
        float t = payoff[2 * j + 1];
        if (t > 0.0f) {
            float s = payoff[2 * j];
            float f = __fsub_rn(t, s);
            float b = belief[j];
            float lik = __fmul_rn(__nv_powf(p, s), __nv_powf(q, f));
            float alt = __fmul_rn(__nv_powf(q, s), __nv_powf(p, f));
            float delta = fabsf(__fsub_rn(prior, b));
            float pl    = __fmul_rn(prior, lik);
            float marg  = __fmaf_rn(__fsub_rn(1.0f, prior), alt, pl);
            float omm   = __fsub_rn(1.0f, marg);
            float bel   = __fdiv_rn(pl, marg);
            float mis   = __fdiv_rn(__fmul_rn(prior, __fsub_rn(1.0f, lik)), omm);
            float u     = __fmul_rn(delta, mst);
            float cert  = fmaxf(__fmaf_rn(-u, omm, 1.0f), 0.0f);
            prior = __fmaf_rn(bel, cert,
                              __fmul_rn(mis, __fsub_rn(1.0f, cert)));
        }
    }
    out[i] = prior;
}

extern "C" void kernel_launch(void* const* d_in, const int* in_sizes, int n_in,
                              void* d_out, int out_size) {
    const float* belief   = (const float*)d_in[0];
    const float* prob     = (const float*)d_in[1];
    const float* mistrust = (const float*)d_in[2];
    const float* payoff   = (const float*)d_in[3];
    const int*   nbr      = (const int*)d_in[4];
    float*       out      = (float*)d_out;

    int n = in_sizes[0];
    int K = (n > 0) ? (in_sizes[4] / n) : 0;

    int grid = (n + BLK - 1) / BLK;

    if (K == 64 && n <= MAXN) {
        pack_kernel<<<grid, BLK>>>(belief, (const float2*)payoff, n);
        fold_kernel<<<grid, BLK>>>(belief, prob, mistrust, nbr, out, n);
    } else {
        fold_generic_kernel<<<grid, BLK>>>(belief, prob, mistrust, payoff, nbr,
                                           out, n, K);
    }
}